// round 3
// baseline (speedup 1.0000x reference)
#include <cuda_runtime.h>
#include <mma.h>
#include <cstdint>
#include <cstddef>

using namespace nvcuda;

#define NN 10000
#define NE 320000
#define FD 256
#define EDF 64

// ---------------- scratch (device globals: no allocation allowed) ----------------
__device__ float g_h0[NN * FD];
__device__ float g_h1[NN * FD];
__device__ float g_Xs[NN * FD];
__device__ float g_Xd[NN * FD];
__device__ int g_rowptr[NN + 1];
__device__ int g_cnt[NN];
__device__ int g_ofs[NN];
__device__ int g_srcs[NE];
__device__ int g_dsts[NE];
__device__ int g_eids[NE];

// ---------------- helpers ----------------
__device__ __forceinline__ float gelu_f(float v) {
    float u = 0.7978845608028654f * (v + 0.044715f * v * v * v);
    float t;
    asm("tanh.approx.f32 %0, %1;" : "=f"(t) : "f"(u));
    return 0.5f * v * (1.0f + t);
}

// ---------------- CSR construction ----------------
__global__ void zero_kernel(int* __restrict__ p, int n) {
    int i = blockIdx.x * blockDim.x + threadIdx.x;
    if (i < n) p[i] = 0;
}

__global__ void hist_kernel(const int* __restrict__ ei, int* __restrict__ cnt, int E) {
    int e = blockIdx.x * blockDim.x + threadIdx.x;
    if (e < E) atomicAdd(&cnt[ei[E + e]], 1);
}

__global__ void scan_kernel(const int* __restrict__ cnt, int* __restrict__ rowptr,
                            int* __restrict__ ofs, int n) {
    __shared__ int part[1024];
    const int PER = 16;
    int t = threadIdx.x;
    int base = t * PER;
    int local[PER];
    int s = 0;
#pragma unroll
    for (int j = 0; j < PER; j++) {
        int idx = base + j;
        int c = (idx < n) ? cnt[idx] : 0;
        local[j] = s;
        s += c;
    }
    part[t] = s;
    __syncthreads();
    for (int off = 1; off < 1024; off <<= 1) {
        int v = (t >= off) ? part[t - off] : 0;
        __syncthreads();
        part[t] += v;
        __syncthreads();
    }
    int pre = (t > 0) ? part[t - 1] : 0;
#pragma unroll
    for (int j = 0; j < PER; j++) {
        int idx = base + j;
        if (idx < n) {
            int v = pre + local[j];
            rowptr[idx] = v;
            ofs[idx] = v;
        }
    }
    if (t == 1023) rowptr[n] = part[1023];
}

__global__ void scatter_kernel(const int* __restrict__ ei, int* __restrict__ ofs,
                               int* __restrict__ srcs, int* __restrict__ dsts,
                               int* __restrict__ eids, int E) {
    int e = blockIdx.x * blockDim.x + threadIdx.x;
    if (e < E) {
        int d = ei[E + e];
        int p = atomicAdd(&ofs[d], 1);
        srcs[p] = ei[e];
        dsts[p] = d;
        eids[p] = e;
    }
}

// ---------------- copy (seed output with hin) ----------------
__global__ void copy_kernel(const float4* __restrict__ a, float4* __restrict__ b, int n4) {
    int i = blockIdx.x * blockDim.x + threadIdx.x;
    if (i < n4) b[i] = a[i];
}

// ---------------- node GEMM: C = op(A[M,256] @ B[256,256] + bias [+resid]) ----------------
// grid.y in [0, 2*4): sel = y>>2 picks (B0,C0) vs (B1,C1); cg = y&3 picks 64-col group.
// B fragments loaded directly from global (L1-resident weights). A tile double-buffered via regs.
__global__ void __launch_bounds__(256) gemm_node(
    const float* __restrict__ A,
    const float* __restrict__ B0, const float* __restrict__ B1,
    const float* __restrict__ bias,
    const float* __restrict__ resid,
    float* __restrict__ C0, float* __restrict__ C1,
    int M, int dogelu)
{
    constexpr int BM = 128, BN = 64, LDA = 36;
    __shared__ __align__(16) float sm[BM * BN];  // 32 KB: A-tile (first 4608) then C-tile
    float* As = sm;
    float* Cs = sm;

    int tid = threadIdx.x;
    int warp = tid >> 5;
    int wm = warp >> 1, wn = warp & 1;
    int bm = blockIdx.x * BM;
    int sel = blockIdx.y >> 2;
    int cg = blockIdx.y & 3;
    const float* B = sel ? B1 : B0;
    float* C = sel ? C1 : C0;
    int bn = cg * BN;

    int lr = tid >> 3, lc = (tid & 7) << 2;

    wmma::fragment<wmma::accumulator, 16, 16, 8, float> acc[2][2];
#pragma unroll
    for (int i = 0; i < 2; i++)
#pragma unroll
        for (int j = 0; j < 2; j++) wmma::fill_fragment(acc[i][j], 0.0f);

    float4 pre[4];
#pragma unroll
    for (int p = 0; p < 4; p++) {
        int grow = bm + lr + 32 * p;
        pre[p] = (grow < M) ? *(const float4*)(A + (size_t)grow * FD + lc)
                            : make_float4(0.f, 0.f, 0.f, 0.f);
    }
#pragma unroll
    for (int p = 0; p < 4; p++) *(float4*)(As + (lr + 32 * p) * LDA + lc) = pre[p];
    __syncthreads();

    for (int k0 = 0; k0 < FD; k0 += 32) {
        bool more = (k0 + 32) < FD;
        float4 nxt[4];
        if (more) {
#pragma unroll
            for (int p = 0; p < 4; p++) {
                int grow = bm + lr + 32 * p;
                nxt[p] = (grow < M) ? *(const float4*)(A + (size_t)grow * FD + k0 + 32 + lc)
                                    : make_float4(0.f, 0.f, 0.f, 0.f);
            }
        }
#pragma unroll
        for (int kk = 0; kk < 32; kk += 8) {
            wmma::fragment<wmma::matrix_a, 16, 16, 8, wmma::precision::tf32, wmma::row_major> a[2];
            wmma::fragment<wmma::matrix_b, 16, 16, 8, wmma::precision::tf32, wmma::row_major> b[2];
#pragma unroll
            for (int i = 0; i < 2; i++) {
                wmma::load_matrix_sync(a[i], As + (wm * 32 + i * 16) * LDA + kk, LDA);
#pragma unroll
                for (int e = 0; e < a[i].num_elements; e++)
                    a[i].x[e] = wmma::__float_to_tf32(a[i].x[e]);
            }
#pragma unroll
            for (int j = 0; j < 2; j++) {
                wmma::load_matrix_sync(b[j], B + (size_t)(k0 + kk) * FD + bn + wn * 32 + j * 16, FD);
#pragma unroll
                for (int e = 0; e < b[j].num_elements; e++)
                    b[j].x[e] = wmma::__float_to_tf32(b[j].x[e]);
            }
#pragma unroll
            for (int i = 0; i < 2; i++)
#pragma unroll
                for (int j = 0; j < 2; j++)
                    wmma::mma_sync(acc[i][j], a[i], b[j], acc[i][j]);
        }
        __syncthreads();
        if (more) {
#pragma unroll
            for (int p = 0; p < 4; p++) *(float4*)(As + (lr + 32 * p) * LDA + lc) = nxt[p];
            __syncthreads();
        }
    }

#pragma unroll
    for (int i = 0; i < 2; i++)
#pragma unroll
        for (int j = 0; j < 2; j++)
            wmma::store_matrix_sync(Cs + (wm * 32 + i * 16) * BN + wn * 32 + j * 16,
                                    acc[i][j], BN, wmma::mem_row_major);
    __syncthreads();
    for (int idx = tid; idx < BM * BN; idx += 256) {
        int r = idx >> 6, c = idx & 63;
        int grow = bm + r;
        if (grow >= M) continue;
        float v = Cs[idx];
        if (bias) v += bias[bn + c];
        if (dogelu) v = gelu_f(v);
        if (resid) v += resid[(size_t)grow * FD + bn + c];
        C[(size_t)grow * FD + bn + c] = v;
    }
}

// ---------------- fused edge kernel ----------------
// Per block: 128 CSR edges x one 64-col group.
// M = gelu(ef[eids] @ W_ef[:,cols] + b + Xs[src] + Xd[dst]); segmented-sum by dst -> atomicAdd.
__global__ void __launch_bounds__(256) edge_fused(
    const float* __restrict__ ef,
    const float* __restrict__ Wef,   // [64, 256]
    const float* __restrict__ bias,  // [256]
    const float* __restrict__ Xs, const float* __restrict__ Xd,
    float* __restrict__ out,         // pre-seeded with hin
    int E)
{
    constexpr int CH = 128, LDA = 68;
    __shared__ __align__(16) float Aef[CH * LDA];  // 34816 B; reused as C tile
    __shared__ int s_src[CH], s_dst[CH];

    int tid = threadIdx.x;
    int base = blockIdx.x * CH;
    int cg = blockIdx.y;
    int warp = tid >> 5;
    int wm = warp >> 1, wn = warp & 1;

    // chunk metadata
    __shared__ int s_eid[CH];
    if (tid < CH) {
        int i = base + tid;
        bool v = i < E;
        s_eid[tid] = v ? g_eids[i] : 0;
        s_src[tid] = v ? g_srcs[i] : 0;
        s_dst[tid] = v ? g_dsts[i] : -1;
    }
    __syncthreads();

    // gather ef rows (64 floats each) into Aef
#pragma unroll
    for (int p = 0; p < 8; p++) {
        int j = tid + 256 * p;      // 0..2047
        int row = j >> 4;
        int c4 = j & 15;
        float4 v = make_float4(0.f, 0.f, 0.f, 0.f);
        if (base + row < E)
            v = ((const float4*)(ef + (size_t)s_eid[row] * EDF))[c4];
        *(float4*)(Aef + row * LDA + c4 * 4) = v;
    }
    __syncthreads();

    // wmma: [128,64] x [64,64]
    wmma::fragment<wmma::accumulator, 16, 16, 8, float> acc[2][2];
#pragma unroll
    for (int i = 0; i < 2; i++)
#pragma unroll
        for (int j = 0; j < 2; j++) wmma::fill_fragment(acc[i][j], 0.0f);

#pragma unroll
    for (int kk = 0; kk < EDF; kk += 8) {
        wmma::fragment<wmma::matrix_a, 16, 16, 8, wmma::precision::tf32, wmma::row_major> a[2];
        wmma::fragment<wmma::matrix_b, 16, 16, 8, wmma::precision::tf32, wmma::row_major> b[2];
#pragma unroll
        for (int i = 0; i < 2; i++) {
            wmma::load_matrix_sync(a[i], Aef + (wm * 32 + i * 16) * LDA + kk, LDA);
#pragma unroll
            for (int e = 0; e < a[i].num_elements; e++)
                a[i].x[e] = wmma::__float_to_tf32(a[i].x[e]);
        }
#pragma unroll
        for (int j = 0; j < 2; j++) {
            wmma::load_matrix_sync(b[j], Wef + (size_t)kk * FD + cg * 64 + wn * 32 + j * 16, FD);
#pragma unroll
            for (int e = 0; e < b[j].num_elements; e++)
                b[j].x[e] = wmma::__float_to_tf32(b[j].x[e]);
        }
#pragma unroll
        for (int i = 0; i < 2; i++)
#pragma unroll
            for (int j = 0; j < 2; j++)
                wmma::mma_sync(acc[i][j], a[i], b[j], acc[i][j]);
    }
    __syncthreads();  // all a-frag reads of Aef complete before overwrite

    float* Cs = Aef;  // reuse, ld = LDA
#pragma unroll
    for (int i = 0; i < 2; i++)
#pragma unroll
        for (int j = 0; j < 2; j++)
            wmma::store_matrix_sync(Cs + (wm * 32 + i * 16) * LDA + wn * 32 + j * 16,
                                    acc[i][j], LDA, wmma::mem_row_major);
    __syncthreads();

    // epilogue: add Xs[src]+Xd[dst], gelu, segmented reduce by dst
    int c = tid & 63;
    int q = tid >> 6;
    float bv = bias[cg * 64 + c];
    float accv = 0.0f;
    int prev = -2;
#pragma unroll 4
    for (int r = 0; r < 32; r++) {
        int row = q * 32 + r;
        if (base + row >= E) break;
        int d = s_dst[row];
        float v = Cs[row * LDA + c] + bv
                + Xs[(size_t)s_src[row] * FD + cg * 64 + c]
                + Xd[(size_t)d * FD + cg * 64 + c];
        v = gelu_f(v);
        if (d != prev) {
            if (prev >= 0) atomicAdd(&out[(size_t)prev * FD + cg * 64 + c], accv);
            accv = 0.0f;
            prev = d;
        }
        accv += v;
    }
    if (prev >= 0) atomicAdd(&out[(size_t)prev * FD + cg * 64 + c], accv);
}

// ---------------- launch ----------------
extern "C" void kernel_launch(void* const* d_in, const int* in_sizes, int n_in,
                              void* d_out, int out_size) {
    const float* x    = (const float*)d_in[0];
    const int* ei     = (const int*)d_in[1];   // int32 (JAX x64 disabled)
    const float* ef   = (const float*)d_in[2];
    const float* Wff1 = (const float*)d_in[3];
    const float* bff1 = (const float*)d_in[4];
    const float* Wmp1 = (const float*)d_in[5];
    const float* bmp1 = (const float*)d_in[6];
    const float* Wmp2 = (const float*)d_in[7];
    const float* bmp2 = (const float*)d_in[8];
    const float* Wff2 = (const float*)d_in[9];
    const float* bff2 = (const float*)d_in[10];

    int N = in_sizes[0] / FD;
    int E = in_sizes[1] / 2;

    float *h0, *h1, *Xs, *Xd;
    int *rowptr, *cnt, *ofs, *srcs, *dsts, *eids;
    cudaGetSymbolAddress((void**)&h0, g_h0);
    cudaGetSymbolAddress((void**)&h1, g_h1);
    cudaGetSymbolAddress((void**)&Xs, g_Xs);
    cudaGetSymbolAddress((void**)&Xd, g_Xd);
    cudaGetSymbolAddress((void**)&rowptr, g_rowptr);
    cudaGetSymbolAddress((void**)&cnt, g_cnt);
    cudaGetSymbolAddress((void**)&ofs, g_ofs);
    cudaGetSymbolAddress((void**)&srcs, g_srcs);
    cudaGetSymbolAddress((void**)&dsts, g_dsts);
    cudaGetSymbolAddress((void**)&eids, g_eids);

    dim3 thr(256);
    int eb = (E + 255) / 256;
    int n4 = N * FD / 4;

    // CSR by dst
    zero_kernel<<<(N + 255) / 256, thr>>>(cnt, N);
    hist_kernel<<<eb, thr>>>(ei, cnt, E);
    scan_kernel<<<1, 1024>>>(cnt, rowptr, ofs, N);
    scatter_kernel<<<eb, thr>>>(ei, ofs, srcs, dsts, eids, E);

    dim3 gN((N + 127) / 128, 4);
    dim3 gN2((N + 127) / 128, 8);
    dim3 gEg((E + 127) / 128, 4);

    // FFN1: h0 = gelu(x @ W_ff1 + b_ff1)
    gemm_node<<<gN, thr>>>(x, Wff1, nullptr, bff1, nullptr, h0, nullptr, N, 1);

    // MP1: Xs = h0 @ W_src1, Xd = h0 @ W_dst1 (one launch)
    gemm_node<<<gN2, thr>>>(h0, Wmp1, Wmp1 + FD * FD, nullptr, nullptr, Xs, Xd, N, 0);
    copy_kernel<<<(n4 + 255) / 256, thr>>>((const float4*)h0, (float4*)h1, n4);
    edge_fused<<<gEg, thr>>>(ef, Wmp1 + 2 * FD * FD, bmp1, Xs, Xd, h1, E);

    // MP2
    gemm_node<<<gN2, thr>>>(h1, Wmp2, Wmp2 + FD * FD, nullptr, nullptr, Xs, Xd, N, 0);
    copy_kernel<<<(n4 + 255) / 256, thr>>>((const float4*)h1, (float4*)h0, n4);
    edge_fused<<<gEg, thr>>>(ef, Wmp2 + 2 * FD * FD, bmp2, Xs, Xd, h0, E);

    // FFN2 + residual: out = x + h0 @ W_ff2 + b_ff2
    gemm_node<<<gN, thr>>>(h0, Wff2, nullptr, bff2, x, (float*)d_out, nullptr, N, 0);
}

// round 4
// speedup vs baseline: 1.3661x; 1.3661x over previous
#include <cuda_runtime.h>
#include <mma.h>
#include <cstdint>
#include <cstddef>

using namespace nvcuda;

#define NN 10000
#define NE 320000
#define FD 256
#define EDF 64

// ---------------- scratch ----------------
__device__ float g_h0[NN * FD];
__device__ float g_h1[NN * FD];
__device__ float g_Xs[NN * FD];
__device__ float g_Xd[NN * FD];
__device__ int g_rowptr[NN + 1];
__device__ int g_cnt[NN];
__device__ int g_ofs[NN];
__device__ int g_srcs[NE];
__device__ int g_dsts[NE];
__device__ int g_eids[NE];

__device__ __forceinline__ float gelu_f(float v) {
    float u = 0.7978845608028654f * (v + 0.044715f * v * v * v);
    float t;
    asm("tanh.approx.f32 %0, %1;" : "=f"(t) : "f"(u));
    return 0.5f * v * (1.0f + t);
}

// ---------------- CSR construction ----------------
__global__ void zero_kernel(int* __restrict__ p, int n) {
    int i = blockIdx.x * blockDim.x + threadIdx.x;
    if (i < n) p[i] = 0;
}

__global__ void hist_kernel(const int* __restrict__ ei, int* __restrict__ cnt, int E) {
    int e = blockIdx.x * blockDim.x + threadIdx.x;
    if (e < E) atomicAdd(&cnt[ei[E + e]], 1);
}

__global__ void scan_kernel(const int* __restrict__ cnt, int* __restrict__ rowptr,
                            int* __restrict__ ofs, int n) {
    __shared__ int part[1024];
    const int PER = 16;
    int t = threadIdx.x;
    int base = t * PER;
    int local[PER];
    int s = 0;
#pragma unroll
    for (int j = 0; j < PER; j++) {
        int idx = base + j;
        int c = (idx < n) ? cnt[idx] : 0;
        local[j] = s;
        s += c;
    }
    part[t] = s;
    __syncthreads();
    for (int off = 1; off < 1024; off <<= 1) {
        int v = (t >= off) ? part[t - off] : 0;
        __syncthreads();
        part[t] += v;
        __syncthreads();
    }
    int pre = (t > 0) ? part[t - 1] : 0;
#pragma unroll
    for (int j = 0; j < PER; j++) {
        int idx = base + j;
        if (idx < n) {
            int v = pre + local[j];
            rowptr[idx] = v;
            ofs[idx] = v;
        }
    }
    if (t == 1023) rowptr[n] = part[1023];
}

__global__ void scatter_kernel(const int* __restrict__ ei, int* __restrict__ ofs,
                               int* __restrict__ srcs, int* __restrict__ dsts,
                               int* __restrict__ eids, int E) {
    int e = blockIdx.x * blockDim.x + threadIdx.x;
    if (e < E) {
        int d = ei[E + e];
        int p = atomicAdd(&ofs[d], 1);
        srcs[p] = ei[e];
        dsts[p] = d;
        eids[p] = e;
    }
}

__global__ void copy_kernel(const float4* __restrict__ a, float4* __restrict__ b, int n4) {
    int i = blockIdx.x * blockDim.x + threadIdx.x;
    if (i < n4) b[i] = a[i];
}

// ---------------- node GEMM: C = op(A[M,256] @ B[256,256] + bias [+resid]) ----------------
// grid.y: sel = y>>2 picks (B0,C0)/(B1,C1); cg = y&3 picks 64-col group.
// A and B tiles staged in smem; next tiles prefetched into registers (double buffer).
__global__ void __launch_bounds__(256) gemm_node(
    const float* __restrict__ A,
    const float* __restrict__ B0, const float* __restrict__ B1,
    const float* __restrict__ bias,
    const float* __restrict__ resid,
    float* __restrict__ C0, float* __restrict__ C1,
    int M, int dogelu)
{
    constexpr int BM = 128, BN = 64, BK = 32;
    constexpr int LDA = 36, LDB = 68;
    __shared__ __align__(16) float sm[BM * BN];  // 32 KB; As+Bs then reused as C tile
    float* As = sm;                   // 128*36 = 4608 floats
    float* Bs = sm + BM * LDA;        // 32*68 = 2176 floats (4608+2176 <= 8192)
    float* Cs = sm;

    int tid = threadIdx.x;
    int warp = tid >> 5;
    int wm = warp >> 1, wn = warp & 1;
    int bm = blockIdx.x * BM;
    int sel = blockIdx.y >> 2;
    int cg = blockIdx.y & 3;
    const float* B = sel ? B1 : B0;
    float* C = sel ? C1 : C0;
    int bn = cg * BN;

    int lra = tid >> 3, lca = (tid & 7) << 2;      // A tile loader: 32 rows x 8 float4
    int lrb = tid >> 4, lcb = (tid & 15) << 2;     // B tile loader: 16 rows x 16 float4

    wmma::fragment<wmma::accumulator, 16, 16, 8, float> acc[2][2];
#pragma unroll
    for (int i = 0; i < 2; i++)
#pragma unroll
        for (int j = 0; j < 2; j++) wmma::fill_fragment(acc[i][j], 0.0f);

    // preload k0 = 0 tiles
    float4 pa[4], pb[2];
#pragma unroll
    for (int p = 0; p < 4; p++) {
        int grow = bm + lra + 32 * p;
        pa[p] = (grow < M) ? *(const float4*)(A + (size_t)grow * FD + lca)
                           : make_float4(0.f, 0.f, 0.f, 0.f);
    }
#pragma unroll
    for (int p = 0; p < 2; p++)
        pb[p] = *(const float4*)(B + (size_t)(lrb + 16 * p) * FD + bn + lcb);
#pragma unroll
    for (int p = 0; p < 4; p++) *(float4*)(As + (lra + 32 * p) * LDA + lca) = pa[p];
#pragma unroll
    for (int p = 0; p < 2; p++) *(float4*)(Bs + (lrb + 16 * p) * LDB + lcb) = pb[p];
    __syncthreads();

    for (int k0 = 0; k0 < FD; k0 += BK) {
        bool more = (k0 + BK) < FD;
        if (more) {
#pragma unroll
            for (int p = 0; p < 4; p++) {
                int grow = bm + lra + 32 * p;
                pa[p] = (grow < M) ? *(const float4*)(A + (size_t)grow * FD + k0 + BK + lca)
                                   : make_float4(0.f, 0.f, 0.f, 0.f);
            }
#pragma unroll
            for (int p = 0; p < 2; p++)
                pb[p] = *(const float4*)(B + (size_t)(k0 + BK + lrb + 16 * p) * FD + bn + lcb);
        }
#pragma unroll
        for (int kk = 0; kk < BK; kk += 8) {
            wmma::fragment<wmma::matrix_a, 16, 16, 8, wmma::precision::tf32, wmma::row_major> a[2];
            wmma::fragment<wmma::matrix_b, 16, 16, 8, wmma::precision::tf32, wmma::row_major> b[2];
#pragma unroll
            for (int i = 0; i < 2; i++) {
                wmma::load_matrix_sync(a[i], As + (wm * 32 + i * 16) * LDA + kk, LDA);
#pragma unroll
                for (int e = 0; e < a[i].num_elements; e++)
                    a[i].x[e] = wmma::__float_to_tf32(a[i].x[e]);
            }
#pragma unroll
            for (int j = 0; j < 2; j++) {
                wmma::load_matrix_sync(b[j], Bs + kk * LDB + wn * 32 + j * 16, LDB);
#pragma unroll
                for (int e = 0; e < b[j].num_elements; e++)
                    b[j].x[e] = wmma::__float_to_tf32(b[j].x[e]);
            }
#pragma unroll
            for (int i = 0; i < 2; i++)
#pragma unroll
                for (int j = 0; j < 2; j++)
                    wmma::mma_sync(acc[i][j], a[i], b[j], acc[i][j]);
        }
        __syncthreads();
        if (more) {
#pragma unroll
            for (int p = 0; p < 4; p++) *(float4*)(As + (lra + 32 * p) * LDA + lca) = pa[p];
#pragma unroll
            for (int p = 0; p < 2; p++) *(float4*)(Bs + (lrb + 16 * p) * LDB + lcb) = pb[p];
            __syncthreads();
        }
    }

#pragma unroll
    for (int i = 0; i < 2; i++)
#pragma unroll
        for (int j = 0; j < 2; j++)
            wmma::store_matrix_sync(Cs + (wm * 32 + i * 16) * BN + wn * 32 + j * 16,
                                    acc[i][j], BN, wmma::mem_row_major);
    __syncthreads();
    for (int idx = tid; idx < BM * BN; idx += 256) {
        int r = idx >> 6, c = idx & 63;
        int grow = bm + r;
        if (grow >= M) continue;
        float v = Cs[idx];
        if (bias) v += bias[bn + c];
        if (dogelu) v = gelu_f(v);
        if (resid) v += resid[(size_t)grow * FD + bn + c];
        C[(size_t)grow * FD + bn + c] = v;
    }
}

// ---------------- fused edge kernel ----------------
// Per block: 128 CSR-sorted edges x one 64-col group.
// M = gelu(ef[eids] @ W_ef[:,cols] + b + Xs[src] + Xd[dst]); segmented-sum by dst -> atomicAdd.
__global__ void __launch_bounds__(256) edge_fused(
    const float* __restrict__ ef,
    const float* __restrict__ Wef,   // [64, 256]
    const float* __restrict__ bias,  // [256]
    const float* __restrict__ Xs, const float* __restrict__ Xd,
    float* __restrict__ out,         // pre-seeded with hin
    int E)
{
    constexpr int CH = 128, LDA = 68;
    __shared__ __align__(16) float Aef[CH * LDA];  // reused as C tile
    __shared__ int s_src[CH], s_dst[CH], s_eid[CH];

    int tid = threadIdx.x;
    int base = blockIdx.x * CH;
    int cg = blockIdx.y;
    int warp = tid >> 5;
    int wm = warp >> 1, wn = warp & 1;

    if (tid < CH) {
        int i = base + tid;
        bool v = i < E;
        s_eid[tid] = v ? g_eids[i] : 0;
        s_src[tid] = v ? g_srcs[i] : 0;
        s_dst[tid] = v ? g_dsts[i] : -1;
    }
    __syncthreads();

    // gather ef rows (64 floats each)
#pragma unroll
    for (int p = 0; p < 8; p++) {
        int j = tid + 256 * p;
        int row = j >> 4;
        int c4 = j & 15;
        float4 v = make_float4(0.f, 0.f, 0.f, 0.f);
        if (base + row < E)
            v = ((const float4*)(ef + (size_t)s_eid[row] * EDF))[c4];
        *(float4*)(Aef + row * LDA + c4 * 4) = v;
    }
    __syncthreads();

    wmma::fragment<wmma::accumulator, 16, 16, 8, float> acc[2][2];
#pragma unroll
    for (int i = 0; i < 2; i++)
#pragma unroll
        for (int j = 0; j < 2; j++) wmma::fill_fragment(acc[i][j], 0.0f);

#pragma unroll
    for (int kk = 0; kk < EDF; kk += 8) {
        wmma::fragment<wmma::matrix_a, 16, 16, 8, wmma::precision::tf32, wmma::row_major> a[2];
        wmma::fragment<wmma::matrix_b, 16, 16, 8, wmma::precision::tf32, wmma::row_major> b[2];
#pragma unroll
        for (int i = 0; i < 2; i++) {
            wmma::load_matrix_sync(a[i], Aef + (wm * 32 + i * 16) * LDA + kk, LDA);
#pragma unroll
            for (int e = 0; e < a[i].num_elements; e++)
                a[i].x[e] = wmma::__float_to_tf32(a[i].x[e]);
        }
#pragma unroll
        for (int j = 0; j < 2; j++) {
            wmma::load_matrix_sync(b[j], Wef + (size_t)kk * FD + cg * 64 + wn * 32 + j * 16, FD);
#pragma unroll
            for (int e = 0; e < b[j].num_elements; e++)
                b[j].x[e] = wmma::__float_to_tf32(b[j].x[e]);
        }
#pragma unroll
        for (int i = 0; i < 2; i++)
#pragma unroll
            for (int j = 0; j < 2; j++)
                wmma::mma_sync(acc[i][j], a[i], b[j], acc[i][j]);
    }
    __syncthreads();

    float* Cs = Aef;
#pragma unroll
    for (int i = 0; i < 2; i++)
#pragma unroll
        for (int j = 0; j < 2; j++)
            wmma::store_matrix_sync(Cs + (wm * 32 + i * 16) * LDA + wn * 32 + j * 16,
                                    acc[i][j], LDA, wmma::mem_row_major);
    __syncthreads();

    // epilogue: front-batched Xs gathers; Xd loaded once per dst segment (CSR-sorted)
    int c = tid & 63;
    int q = tid >> 6;
    float bv = bias[cg * 64 + c];
    float accv = 0.0f, xdv = 0.0f;
    int prev = -2;
#pragma unroll
    for (int r0 = 0; r0 < 32; r0 += 8) {
        float xs[8];
#pragma unroll
        for (int r = 0; r < 8; r++) {
            int row = q * 32 + r0 + r;
            xs[r] = (base + row < E)
                  ? Xs[(size_t)s_src[row] * FD + cg * 64 + c] : 0.0f;
        }
#pragma unroll
        for (int r = 0; r < 8; r++) {
            int row = q * 32 + r0 + r;
            if (base + row >= E) break;
            int d = s_dst[row];
            if (d != prev) {
                if (prev >= 0) atomicAdd(&out[(size_t)prev * FD + cg * 64 + c], accv);
                accv = 0.0f;
                prev = d;
                xdv = Xd[(size_t)d * FD + cg * 64 + c];
            }
            accv += gelu_f(Cs[row * LDA + c] + bv + xs[r] + xdv);
        }
    }
    if (prev >= 0) atomicAdd(&out[(size_t)prev * FD + cg * 64 + c], accv);
}

// ---------------- launch ----------------
extern "C" void kernel_launch(void* const* d_in, const int* in_sizes, int n_in,
                              void* d_out, int out_size) {
    const float* x    = (const float*)d_in[0];
    const int* ei     = (const int*)d_in[1];   // int32 (JAX x64 disabled)
    const float* ef   = (const float*)d_in[2];
    const float* Wff1 = (const float*)d_in[3];
    const float* bff1 = (const float*)d_in[4];
    const float* Wmp1 = (const float*)d_in[5];
    const float* bmp1 = (const float*)d_in[6];
    const float* Wmp2 = (const float*)d_in[7];
    const float* bmp2 = (const float*)d_in[8];
    const float* Wff2 = (const float*)d_in[9];
    const float* bff2 = (const float*)d_in[10];

    int N = in_sizes[0] / FD;
    int E = in_sizes[1] / 2;

    float *h0, *h1, *Xs, *Xd;
    int *rowptr, *cnt, *ofs, *srcs, *dsts, *eids;
    cudaGetSymbolAddress((void**)&h0, g_h0);
    cudaGetSymbolAddress((void**)&h1, g_h1);
    cudaGetSymbolAddress((void**)&Xs, g_Xs);
    cudaGetSymbolAddress((void**)&Xd, g_Xd);
    cudaGetSymbolAddress((void**)&rowptr, g_rowptr);
    cudaGetSymbolAddress((void**)&cnt, g_cnt);
    cudaGetSymbolAddress((void**)&ofs, g_ofs);
    cudaGetSymbolAddress((void**)&srcs, g_srcs);
    cudaGetSymbolAddress((void**)&dsts, g_dsts);
    cudaGetSymbolAddress((void**)&eids, g_eids);

    dim3 thr(256);
    int eb = (E + 255) / 256;
    int n4 = N * FD / 4;

    dim3 gN((N + 127) / 128, 4);
    dim3 gN2((N + 127) / 128, 8);
    dim3 gEg((E + 127) / 128, 4);

    // CSR prefix (1-3), FFN1 moved to slot 4 as a profiler probe (no dependency on scatter)
    zero_kernel<<<(N + 255) / 256, thr>>>(cnt, N);                          // 1
    hist_kernel<<<eb, thr>>>(ei, cnt, E);                                   // 2
    scan_kernel<<<1, 1024>>>(cnt, rowptr, ofs, N);                          // 3
    gemm_node<<<gN, thr>>>(x, Wff1, nullptr, bff1, nullptr, h0, nullptr, N, 1);  // 4: FFN1
    scatter_kernel<<<eb, thr>>>(ei, ofs, srcs, dsts, eids, E);              // 5

    // MP1
    gemm_node<<<gN2, thr>>>(h0, Wmp1, Wmp1 + FD * FD, nullptr, nullptr, Xs, Xd, N, 0);
    copy_kernel<<<(n4 + 255) / 256, thr>>>((const float4*)h0, (float4*)h1, n4);
    edge_fused<<<gEg, thr>>>(ef, Wmp1 + 2 * FD * FD, bmp1, Xs, Xd, h1, E);

    // MP2
    gemm_node<<<gN2, thr>>>(h1, Wmp2, Wmp2 + FD * FD, nullptr, nullptr, Xs, Xd, N, 0);
    copy_kernel<<<(n4 + 255) / 256, thr>>>((const float4*)h1, (float4*)h0, n4);
    edge_fused<<<gEg, thr>>>(ef, Wmp2 + 2 * FD * FD, bmp2, Xs, Xd, h0, E);

    // FFN2 + residual
    gemm_node<<<gN, thr>>>(h0, Wff2, nullptr, bff2, x, (float*)d_out, nullptr, N, 0);
}